// round 4
// baseline (speedup 1.0000x reference)
#include <cuda_runtime.h>
#include <math.h>

// Problem constants (fixed by the dataset)
#define BGRAPHS 1024
#define DDIM    256
#define KDIM    512   // 2*DDIM (q_star width)
#define NGATES  1024  // 4*DDIM
#define NITERS  6

// Static device scratch (no allocations allowed)
__device__ float g_W[KDIM * NGATES];     // folded weights, k-major, gate-interleaved cols
__device__ float g_bias[NGATES];         // b_ih + b_hh, gate-interleaved
__device__ float g_xB[BGRAPHS * KDIM];   // ping-pong state buffer [h | readout]
__device__ float g_c[BGRAPHS * DDIM];    // LSTM cell state
__device__ int   g_segstart[BGRAPHS + 1];

// ---------------------------------------------------------------------------
// helpers
// ---------------------------------------------------------------------------
__device__ __forceinline__ float fast_sig(float x) {
    return 1.f / (1.f + __expf(-x));
}
__device__ __forceinline__ float fast_tanh(float x) {
    float e2 = __expf(2.f * fabsf(x));
    float t  = 1.f - 2.f / (e2 + 1.f);   // robust for |x| large (e2=inf -> t=1)
    return copysignf(t, x);
}

// ---------------------------------------------------------------------------
// setup kernels
// ---------------------------------------------------------------------------
__global__ void zero_init(float* __restrict__ out) {
    int i = blockIdx.x * blockDim.x + threadIdx.x;   // 524288 threads
    out[i] = 0.f;
    if (i < BGRAPHS * DDIM) g_c[i] = 0.f;
}

// segment_ids sorted ascending -> binary search boundaries
__global__ void seg_bounds(const int* __restrict__ seg, int n) {
    int g = blockIdx.x * blockDim.x + threadIdx.x;
    if (g > BGRAPHS) return;
    int lo = 0, hi = n;
    while (lo < hi) {
        int mid = (lo + hi) >> 1;
        if (seg[mid] < g) lo = mid + 1; else hi = mid;
    }
    g_segstart[g] = lo;
}

// Fold W_ih[:, :256] + W_hh into one matrix; reorder columns so that the 4
// gates of a hidden unit are adjacent: j' = hid*4 + gate  (original row
// j = gate*256 + hid, pytorch gate order i,f,g,o). Stored k-major [512][1024].
__global__ void fold_weights(const float* __restrict__ W_ih,
                             const float* __restrict__ W_hh,
                             const float* __restrict__ b_ih,
                             const float* __restrict__ b_hh) {
    int k = blockIdx.x;          // 0..511
    int t = threadIdx.x;         // j' = 0..1023
    int hid = t >> 2, gate = t & 3;
    int j = gate * DDIM + hid;
    float w = W_ih[j * KDIM + k];
    if (k < DDIM) w += W_hh[j * DDIM + k];
    g_W[k * NGATES + t] = w;
    if (k == 0) g_bias[t] = b_ih[j] + b_hh[j];
}

// ---------------------------------------------------------------------------
// LSTM step: gates = x @ W' ; fused activation epilogue updates c and h.
// x = [h | readout]  (1024 x 512).  BM=128, BN=64, BK=16, 256 threads,
// micro-tile 8x4 -> each thread owns all 4 gates of one hidden unit for
// 8 graphs, so the LSTM epilogue needs no cross-thread exchange.
// ---------------------------------------------------------------------------
#define BM 128
#define BN 64
#define BK 16

__global__ void __launch_bounds__(256) lstm_step(float* __restrict__ outbuf, int it) {
    const float* xin = (it & 1) ? (const float*)g_xB : (const float*)outbuf;
    float* xout      = (it & 1) ? outbuf : (float*)g_xB;

    __shared__ float As[BK][BM + 4];   // +4 pad keeps float4 alignment, kills conflicts
    __shared__ float Bs[BK][BN];

    int t  = threadIdx.x;
    int tx = t & 15, ty = t >> 4;
    int m0 = blockIdx.y * BM;
    int n0 = blockIdx.x * BN;

    float acc[8][4];
#pragma unroll
    for (int i = 0; i < 8; i++)
#pragma unroll
        for (int j = 0; j < 4; j++) acc[i][j] = 0.f;

    for (int k0 = 0; k0 < KDIM; k0 += BK) {
        // A tile: 128 rows x 16 cols, transposed into As[k][m]
#pragma unroll
        for (int i = 0; i < 2; i++) {
            int id  = t * 2 + i;           // 0..511 float4s
            int row = id >> 2;             // 0..127
            int kc  = (id & 3) << 2;       // 0,4,8,12
            float4 a = *(const float4*)&xin[(m0 + row) * KDIM + k0 + kc];
            As[kc + 0][row] = a.x; As[kc + 1][row] = a.y;
            As[kc + 2][row] = a.z; As[kc + 3][row] = a.w;
        }
        // B tile: 16 rows x 64 cols (k-major weights -> coalesced)
        {
            int row = t >> 4, col = (t & 15) << 2;
            *(float4*)&Bs[row][col] = *(const float4*)&g_W[(k0 + row) * NGATES + n0 + col];
        }
        __syncthreads();

#pragma unroll
        for (int k = 0; k < BK; k++) {
            float a[8], b[4];
            *(float4*)&a[0] = *(const float4*)&As[k][ty * 8];
            *(float4*)&a[4] = *(const float4*)&As[k][ty * 8 + 4];
            *(float4*)&b[0] = *(const float4*)&Bs[k][tx * 4];
#pragma unroll
            for (int i = 0; i < 8; i++)
#pragma unroll
                for (int j = 0; j < 4; j++)
                    acc[i][j] = fmaf(a[i], b[j], acc[i][j]);
        }
        __syncthreads();
    }

    // epilogue: 4 consecutive j' = {i,f,g,o} of one hidden unit
    int jp  = n0 + tx * 4;
    int hid = jp >> 2;
    float4 bb = *(const float4*)&g_bias[jp];
#pragma unroll
    for (int i = 0; i < 8; i++) {
        int g = m0 + ty * 8 + i;
        float gi = acc[i][0] + bb.x;
        float gf = acc[i][1] + bb.y;
        float gg = acc[i][2] + bb.z;
        float go = acc[i][3] + bb.w;
        float cold = g_c[g * DDIM + hid];
        float cn = fast_sig(gf) * cold + fast_sig(gi) * fast_tanh(gg);
        float hn = fast_sig(go) * fast_tanh(cn);
        g_c[g * DDIM + hid]  = cn;
        xout[g * KDIM + hid] = hn;
    }
}

// ---------------------------------------------------------------------------
// Fused attention + readout, single pass over feat via online softmax with a
// running weighted vector. One block per graph (segments sorted). Each warp
// keeps (m, s, v[256]) with v distributed 8 floats/lane in registers; warp
// states merged in shared at the end. Writes readout into x[:, 256:512].
// ---------------------------------------------------------------------------
__global__ void __launch_bounds__(256) attn_pass(const float* __restrict__ feat,
                                                 float* __restrict__ outbuf, int it) {
    float* x = (it & 1) ? outbuf : (float*)g_xB;   // the iteration's OUT buffer

    int g    = blockIdx.x;
    int t    = threadIdx.x;
    int wid  = t >> 5;
    int lane = t & 31;

    const float* q = x + g * KDIM;                 // q = h just written by lstm_step
    float4 qa = *(const float4*)&q[lane * 4];
    float4 qb = *(const float4*)&q[128 + lane * 4];

    int ns = g_segstart[g], ne = g_segstart[g + 1];

    float m = -INFINITY, s = 0.f;
    float4 va = make_float4(0.f, 0.f, 0.f, 0.f);
    float4 vb = make_float4(0.f, 0.f, 0.f, 0.f);

    for (int n = ns + wid; n < ne; n += 8) {
        const float* f = feat + (size_t)n * DDIM;
        float4 f1 = *(const float4*)&f[lane * 4];
        float4 f2 = *(const float4*)&f[128 + lane * 4];

        float e = f1.x * qa.x;
        e = fmaf(f1.y, qa.y, e); e = fmaf(f1.z, qa.z, e); e = fmaf(f1.w, qa.w, e);
        e = fmaf(f2.x, qb.x, e); e = fmaf(f2.y, qb.y, e);
        e = fmaf(f2.z, qb.z, e); e = fmaf(f2.w, qb.w, e);
        e += __shfl_xor_sync(0xffffffffu, e, 16);
        e += __shfl_xor_sync(0xffffffffu, e, 8);
        e += __shfl_xor_sync(0xffffffffu, e, 4);
        e += __shfl_xor_sync(0xffffffffu, e, 2);
        e += __shfl_xor_sync(0xffffffffu, e, 1);
        // e identical across all lanes -> uniform branch
        if (e > m) {
            float sc = __expf(m - e);              // exp(-inf)=0 on first node
            s = fmaf(s, sc, 1.f);
            va.x = fmaf(va.x, sc, f1.x); va.y = fmaf(va.y, sc, f1.y);
            va.z = fmaf(va.z, sc, f1.z); va.w = fmaf(va.w, sc, f1.w);
            vb.x = fmaf(vb.x, sc, f2.x); vb.y = fmaf(vb.y, sc, f2.y);
            vb.z = fmaf(vb.z, sc, f2.z); vb.w = fmaf(vb.w, sc, f2.w);
            m = e;
        } else {
            float w = __expf(e - m);
            s += w;
            va.x = fmaf(w, f1.x, va.x); va.y = fmaf(w, f1.y, va.y);
            va.z = fmaf(w, f1.z, va.z); va.w = fmaf(w, f1.w, va.w);
            vb.x = fmaf(w, f2.x, vb.x); vb.y = fmaf(w, f2.y, vb.y);
            vb.z = fmaf(w, f2.z, vb.z); vb.w = fmaf(w, f2.w, vb.w);
        }
    }

    __shared__ float sm_m[8], sm_s[8];
    __shared__ float sm_v[8][256];
    if (lane == 0) { sm_m[wid] = m; sm_s[wid] = s; }
    *(float4*)&sm_v[wid][lane * 4]       = va;
    *(float4*)&sm_v[wid][128 + lane * 4] = vb;
    __syncthreads();

    // each thread finalizes one output dim
    float M = sm_m[0];
#pragma unroll
    for (int w = 1; w < 8; w++) M = fmaxf(M, sm_m[w]);
    float S = 0.f, val = 0.f;
#pragma unroll
    for (int w = 0; w < 8; w++) {
        float fw = (sm_s[w] > 0.f) ? __expf(sm_m[w] - M) : 0.f;  // guard empty warps (-inf - -inf)
        S = fmaf(sm_s[w], fw, S);
        val = fmaf(sm_v[w][t], fw, val);
    }
    x[g * KDIM + DDIM + t] = (S > 0.f) ? val / S : 0.f;          // empty graph -> 0
}

// ---------------------------------------------------------------------------
// launch
// ---------------------------------------------------------------------------
extern "C" void kernel_launch(void* const* d_in, const int* in_sizes, int n_in,
                              void* d_out, int out_size) {
    const float* feat = (const float*)d_in[0];
    const float* W_ih = (const float*)d_in[1];
    const float* W_hh = (const float*)d_in[2];
    const float* b_ih = (const float*)d_in[3];
    const float* b_hh = (const float*)d_in[4];
    const int*   seg  = (const int*)d_in[5];
    int N = in_sizes[0] / DDIM;

    float* out = (float*)d_out;   // d_out doubles as ping-pong buffer A: layout == [h | readout]

    zero_init<<<1024, 512>>>(out);
    seg_bounds<<<9, 128>>>(seg, N);
    fold_weights<<<KDIM, NGATES>>>(W_ih, W_hh, b_ih, b_hh);

    for (int it = 0; it < NITERS; it++) {
        lstm_step<<<dim3(NGATES / BN, BGRAPHS / BM), 256>>>(out, it);
        attn_pass<<<BGRAPHS, 256>>>(feat, out, it);
    }
    // After it=5 (odd), out holds [h6 | readout6] = q_star. No final copy needed.
}

// round 5
// speedup vs baseline: 1.4030x; 1.4030x over previous
#include <cuda_runtime.h>
#include <cuda_bf16.h>
#include <math.h>

// Problem constants (fixed by the dataset)
#define BGRAPHS 1024
#define DDIM    256
#define KDIM    512   // 2*DDIM (q_star width)
#define NGATES  1024  // 4*DDIM
#define NITERS  6

// Static device scratch (no allocations allowed)
__device__ __nv_bfloat16 g_Wh[NGATES * KDIM];  // folded weights hi, n-major [j'][k]
__device__ __nv_bfloat16 g_Wl[NGATES * KDIM];  // folded weights lo (residual)
__device__ float g_bias[NGATES];               // b_ih + b_hh, gate-interleaved j' = hid*4+gate
__device__ float g_xB[BGRAPHS * KDIM];         // ping-pong state buffer [h | readout]
__device__ float g_c[BGRAPHS * DDIM];          // LSTM cell state
__device__ int   g_segstart[BGRAPHS + 1];

// ---------------------------------------------------------------------------
// helpers
// ---------------------------------------------------------------------------
__device__ __forceinline__ float fast_sig(float x) {
    return 1.f / (1.f + __expf(-x));
}
__device__ __forceinline__ float fast_tanh(float x) {
    float e2 = __expf(2.f * fabsf(x));
    float t  = 1.f - 2.f / (e2 + 1.f);   // robust for |x| large (e2=inf -> t=1)
    return copysignf(t, x);
}
__device__ __forceinline__ unsigned pack_bf2(__nv_bfloat16 a, __nv_bfloat16 b) {
    return (unsigned)__bfloat16_as_ushort(a) | ((unsigned)__bfloat16_as_ushort(b) << 16);
}

// ---------------------------------------------------------------------------
// setup kernels
// ---------------------------------------------------------------------------
__global__ void zero_init(float* __restrict__ out) {
    int i = blockIdx.x * blockDim.x + threadIdx.x;   // 524288 threads
    out[i] = 0.f;
    if (i < BGRAPHS * DDIM) g_c[i] = 0.f;
}

// segment_ids sorted ascending -> binary search boundaries
__global__ void seg_bounds(const int* __restrict__ seg, int n) {
    int g = blockIdx.x * blockDim.x + threadIdx.x;
    if (g > BGRAPHS) return;
    int lo = 0, hi = n;
    while (lo < hi) {
        int mid = (lo + hi) >> 1;
        if (seg[mid] < g) lo = mid + 1; else hi = mid;
    }
    g_segstart[g] = lo;
}

// Fold W_ih[:, :256] + W_hh; reorder rows so that the 4 gates of a hidden
// unit are adjacent: j' = hid*4 + gate (original row j = gate*256 + hid,
// pytorch gate order i,f,g,o). Split into bf16 hi + residual lo, stored
// n-major [j'][k] so GEMM B-tiles load coalesced along k.
__global__ void fold_weights(const float* __restrict__ W_ih,
                             const float* __restrict__ W_hh,
                             const float* __restrict__ b_ih,
                             const float* __restrict__ b_hh) {
    int t = blockIdx.x;          // j' = 0..1023
    int k = threadIdx.x;         // 0..511
    int hid = t >> 2, gate = t & 3;
    int j = gate * DDIM + hid;
    float w = W_ih[j * KDIM + k];
    if (k < DDIM) w += W_hh[j * DDIM + k];
    __nv_bfloat16 wh = __float2bfloat16(w);
    __nv_bfloat16 wl = __float2bfloat16(w - __bfloat162float(wh));
    g_Wh[t * KDIM + k] = wh;
    g_Wl[t * KDIM + k] = wl;
    if (k == 0) g_bias[t] = b_ih[j] + b_hh[j];
}

// ---------------------------------------------------------------------------
// LSTM step on tensor cores: gates = x @ W' with bf16x3 emulated fp32
// (Ah*Bh + Ah*Bl + Al*Bh, fp32 accumulate). CTA 64x64, 4 warps (2x2),
// warp tile 32x32 via mma.m16n8k16. Double-buffered smem, K stages of 32.
// Gate-interleaved columns: lane pairs (qc even/odd) hold (i,f)/(g,o) of
// the same hidden unit -> register-local LSTM epilogue via shfl.
// ---------------------------------------------------------------------------
#define SMN 40   // smem row stride in bf16 (20 words -> conflict-free frags)

#define MMA816(d, a, b) \
    asm volatile("mma.sync.aligned.m16n8k16.row.col.f32.bf16.bf16.f32 " \
                 "{%0,%1,%2,%3},{%4,%5,%6,%7},{%8,%9},{%0,%1,%2,%3};" \
                 : "+f"((d)[0]), "+f"((d)[1]), "+f"((d)[2]), "+f"((d)[3]) \
                 : "r"((a)[0]), "r"((a)[1]), "r"((a)[2]), "r"((a)[3]), \
                   "r"((b)[0]), "r"((b)[1]))

__global__ void __launch_bounds__(128) lstm_mma(float* __restrict__ outbuf, int it) {
    const float* xin = (it & 1) ? (const float*)g_xB : (const float*)outbuf;
    float* xout      = (it & 1) ? outbuf : (float*)g_xB;

    __shared__ __align__(16) __nv_bfloat16 Ah[2][64][SMN], Al[2][64][SMN];
    __shared__ __align__(16) __nv_bfloat16 Bh[2][64][SMN], Bl[2][64][SMN];

    int tid  = threadIdx.x;
    int lane = tid & 31, wid = tid >> 5;
    int qr = lane >> 2, qc = lane & 3;
    int wm = (wid & 1) * 32, wn = (wid >> 1) * 32;
    int m0 = blockIdx.y * 64, n0 = blockIdx.x * 64;

    int arow = tid >> 1;            // 0..63
    int acol = (tid & 1) * 16;      // 0 or 16

    float acc[2][4][4];
#pragma unroll
    for (int mb = 0; mb < 2; mb++)
#pragma unroll
        for (int nb = 0; nb < 4; nb++)
#pragma unroll
            for (int j = 0; j < 4; j++) acc[mb][nb][j] = 0.f;

    // staging registers
    float4 af0, af1, af2, af3;
    uint4 bqh0, bqh1, bql0, bql1;

#define LOAD_STAGE(s) do { \
    const float* ap = xin + (size_t)(m0 + arow) * KDIM + (s) * 32 + acol; \
    af0 = *(const float4*)ap;        af1 = *(const float4*)(ap + 4); \
    af2 = *(const float4*)(ap + 8);  af3 = *(const float4*)(ap + 12); \
    const uint4* bph = (const uint4*)(g_Wh + (size_t)(n0 + arow) * KDIM + (s) * 32 + acol); \
    bqh0 = bph[0]; bqh1 = bph[1]; \
    const uint4* bpl = (const uint4*)(g_Wl + (size_t)(n0 + arow) * KDIM + (s) * 32 + acol); \
    bql0 = bpl[0]; bql1 = bpl[1]; \
} while (0)

#define STORE_STAGE(buf) do { \
    float fv[16]; \
    fv[0]=af0.x; fv[1]=af0.y; fv[2]=af0.z; fv[3]=af0.w; \
    fv[4]=af1.x; fv[5]=af1.y; fv[6]=af1.z; fv[7]=af1.w; \
    fv[8]=af2.x; fv[9]=af2.y; fv[10]=af2.z; fv[11]=af2.w; \
    fv[12]=af3.x; fv[13]=af3.y; fv[14]=af3.z; fv[15]=af3.w; \
    unsigned* dsth = (unsigned*)&Ah[buf][arow][acol]; \
    unsigned* dstl = (unsigned*)&Al[buf][arow][acol]; \
    _Pragma("unroll") \
    for (int w = 0; w < 8; w++) { \
        float v0 = fv[2*w], v1 = fv[2*w+1]; \
        __nv_bfloat16 h0 = __float2bfloat16(v0), h1 = __float2bfloat16(v1); \
        __nv_bfloat16 l0 = __float2bfloat16(v0 - __bfloat162float(h0)); \
        __nv_bfloat16 l1 = __float2bfloat16(v1 - __bfloat162float(h1)); \
        dsth[w] = pack_bf2(h0, h1); \
        dstl[w] = pack_bf2(l0, l1); \
    } \
    *(uint4*)&Bh[buf][arow][acol]     = bqh0; \
    *(uint4*)&Bh[buf][arow][acol + 8] = bqh1; \
    *(uint4*)&Bl[buf][arow][acol]     = bql0; \
    *(uint4*)&Bl[buf][arow][acol + 8] = bql1; \
} while (0)

#define COMPUTE_STAGE(buf) do { \
    _Pragma("unroll") \
    for (int kk = 0; kk < 32; kk += 16) { \
        unsigned ah[2][4], al[2][4], bh[4][2], bl[4][2]; \
        _Pragma("unroll") \
        for (int mb = 0; mb < 2; mb++) { \
            const __nv_bfloat16* ph = &Ah[buf][wm + mb*16 + qr][kk + qc*2]; \
            ah[mb][0] = *(const unsigned*)ph; \
            ah[mb][1] = *(const unsigned*)(ph + 8*SMN); \
            ah[mb][2] = *(const unsigned*)(ph + 8); \
            ah[mb][3] = *(const unsigned*)(ph + 8*SMN + 8); \
            const __nv_bfloat16* pl = &Al[buf][wm + mb*16 + qr][kk + qc*2]; \
            al[mb][0] = *(const unsigned*)pl; \
            al[mb][1] = *(const unsigned*)(pl + 8*SMN); \
            al[mb][2] = *(const unsigned*)(pl + 8); \
            al[mb][3] = *(const unsigned*)(pl + 8*SMN + 8); \
        } \
        _Pragma("unroll") \
        for (int nb = 0; nb < 4; nb++) { \
            const __nv_bfloat16* ph = &Bh[buf][wn + nb*8 + qr][kk + qc*2]; \
            bh[nb][0] = *(const unsigned*)ph; \
            bh[nb][1] = *(const unsigned*)(ph + 8); \
            const __nv_bfloat16* pl = &Bl[buf][wn + nb*8 + qr][kk + qc*2]; \
            bl[nb][0] = *(const unsigned*)pl; \
            bl[nb][1] = *(const unsigned*)(pl + 8); \
        } \
        _Pragma("unroll") \
        for (int mb = 0; mb < 2; mb++) \
        _Pragma("unroll") \
        for (int nb = 0; nb < 4; nb++) { \
            MMA816(acc[mb][nb], ah[mb], bh[nb]); \
            MMA816(acc[mb][nb], ah[mb], bl[nb]); \
            MMA816(acc[mb][nb], al[mb], bh[nb]); \
        } \
    } \
} while (0)

    LOAD_STAGE(0);
    STORE_STAGE(0);
    __syncthreads();

    for (int s = 0; s < 16; s++) {
        int cur = s & 1;
        if (s < 15) LOAD_STAGE(s + 1);       // global loads in flight...
        if (cur == 0) COMPUTE_STAGE(0); else COMPUTE_STAGE(1);  // ...over mma work
        if (s < 15) { if (cur == 0) STORE_STAGE(1); else STORE_STAGE(0); }
        __syncthreads();
    }

    // Epilogue: even-qc lane holds (gi,gf), lane+1 holds (gg,go) of same hid.
#pragma unroll
    for (int mb = 0; mb < 2; mb++)
#pragma unroll
    for (int nb = 0; nb < 4; nb++) {
        float pg0 = __shfl_down_sync(0xffffffffu, acc[mb][nb][0], 1);
        float pg1 = __shfl_down_sync(0xffffffffu, acc[mb][nb][1], 1);
        float pg2 = __shfl_down_sync(0xffffffffu, acc[mb][nb][2], 1);
        float pg3 = __shfl_down_sync(0xffffffffu, acc[mb][nb][3], 1);
        if (!(qc & 1)) {
            int hid = ((n0 + wn) >> 2) + nb * 2 + (qc >> 1);
            float4 bb = *(const float4*)&g_bias[hid * 4];
            int g0 = m0 + wm + mb * 16 + qr;
            {
                float gi = acc[mb][nb][0] + bb.x, gf = acc[mb][nb][1] + bb.y;
                float gg = pg0 + bb.z,            go = pg1 + bb.w;
                float cold = g_c[g0 * DDIM + hid];
                float cn = fast_sig(gf) * cold + fast_sig(gi) * fast_tanh(gg);
                g_c[g0 * DDIM + hid]  = cn;
                xout[g0 * KDIM + hid] = fast_sig(go) * fast_tanh(cn);
            }
            {
                int g1 = g0 + 8;
                float gi = acc[mb][nb][2] + bb.x, gf = acc[mb][nb][3] + bb.y;
                float gg = pg2 + bb.z,            go = pg3 + bb.w;
                float cold = g_c[g1 * DDIM + hid];
                float cn = fast_sig(gf) * cold + fast_sig(gi) * fast_tanh(gg);
                g_c[g1 * DDIM + hid]  = cn;
                xout[g1 * KDIM + hid] = fast_sig(go) * fast_tanh(cn);
            }
        }
    }
}

// ---------------------------------------------------------------------------
// Fused attention + readout, single pass over feat via BRANCHLESS online
// softmax with a running weighted vector, depth-1 prefetch (MLP=2/warp).
// One block per graph (segments sorted); warp states merged in shared.
// ---------------------------------------------------------------------------
__global__ void __launch_bounds__(256) attn_pass(const float* __restrict__ feat,
                                                 float* __restrict__ outbuf, int it) {
    float* x = (it & 1) ? outbuf : (float*)g_xB;   // the iteration's OUT buffer

    int g    = blockIdx.x;
    int t    = threadIdx.x;
    int wid  = t >> 5;
    int lane = t & 31;

    const float* q = x + g * KDIM;                 // q = h just written by lstm_mma
    float4 qa = *(const float4*)&q[lane * 4];
    float4 qb = *(const float4*)&q[128 + lane * 4];

    int ns = g_segstart[g], ne = g_segstart[g + 1];

    float m = -INFINITY, s = 0.f;
    float4 va = make_float4(0.f, 0.f, 0.f, 0.f);
    float4 vb = make_float4(0.f, 0.f, 0.f, 0.f);

    int n = ns + wid;
    float4 c1, c2;
    if (n < ne) {
        const float* f = feat + (size_t)n * DDIM;
        c1 = *(const float4*)&f[lane * 4];
        c2 = *(const float4*)&f[128 + lane * 4];
    }
    while (n < ne) {
        int n2 = n + 8;
        float4 p1, p2;
        if (n2 < ne) {                              // prefetch next node
            const float* f = feat + (size_t)n2 * DDIM;
            p1 = *(const float4*)&f[lane * 4];
            p2 = *(const float4*)&f[128 + lane * 4];
        }
        float e = c1.x * qa.x;
        e = fmaf(c1.y, qa.y, e); e = fmaf(c1.z, qa.z, e); e = fmaf(c1.w, qa.w, e);
        e = fmaf(c2.x, qb.x, e); e = fmaf(c2.y, qb.y, e);
        e = fmaf(c2.z, qb.z, e); e = fmaf(c2.w, qb.w, e);
        e += __shfl_xor_sync(0xffffffffu, e, 16);
        e += __shfl_xor_sync(0xffffffffu, e, 8);
        e += __shfl_xor_sync(0xffffffffu, e, 4);
        e += __shfl_xor_sync(0xffffffffu, e, 2);
        e += __shfl_xor_sync(0xffffffffu, e, 1);
        // branchless online-softmax update (exp(-inf)=0 covers first node)
        float mn = fmaxf(m, e);
        float sc = __expf(m - mn);
        float w  = __expf(e - mn);
        s = fmaf(s, sc, w);
        va.x = fmaf(va.x, sc, w * c1.x); va.y = fmaf(va.y, sc, w * c1.y);
        va.z = fmaf(va.z, sc, w * c1.z); va.w = fmaf(va.w, sc, w * c1.w);
        vb.x = fmaf(vb.x, sc, w * c2.x); vb.y = fmaf(vb.y, sc, w * c2.y);
        vb.z = fmaf(vb.z, sc, w * c2.z); vb.w = fmaf(vb.w, sc, w * c2.w);
        m = mn;
        c1 = p1; c2 = p2;
        n = n2;
    }

    __shared__ float sm_m[8], sm_s[8];
    __shared__ float sm_v[8][256];
    if (lane == 0) { sm_m[wid] = m; sm_s[wid] = s; }
    *(float4*)&sm_v[wid][lane * 4]       = va;
    *(float4*)&sm_v[wid][128 + lane * 4] = vb;
    __syncthreads();

    // each thread finalizes one output dim
    float M = sm_m[0];
#pragma unroll
    for (int w = 1; w < 8; w++) M = fmaxf(M, sm_m[w]);
    float S = 0.f, val = 0.f;
#pragma unroll
    for (int w = 0; w < 8; w++) {
        float fw = (sm_s[w] > 0.f) ? __expf(sm_m[w] - M) : 0.f;  // guard empty warps
        S = fmaf(sm_s[w], fw, S);
        val = fmaf(sm_v[w][t], fw, val);
    }
    x[g * KDIM + DDIM + t] = (S > 0.f) ? val / S : 0.f;          // empty graph -> 0
}

// ---------------------------------------------------------------------------
// launch
// ---------------------------------------------------------------------------
extern "C" void kernel_launch(void* const* d_in, const int* in_sizes, int n_in,
                              void* d_out, int out_size) {
    const float* feat = (const float*)d_in[0];
    const float* W_ih = (const float*)d_in[1];
    const float* W_hh = (const float*)d_in[2];
    const float* b_ih = (const float*)d_in[3];
    const float* b_hh = (const float*)d_in[4];
    const int*   seg  = (const int*)d_in[5];
    int N = in_sizes[0] / DDIM;

    float* out = (float*)d_out;   // d_out doubles as ping-pong buffer: layout == [h | readout]

    zero_init<<<1024, 512>>>(out);
    seg_bounds<<<9, 128>>>(seg, N);
    fold_weights<<<NGATES, KDIM>>>(W_ih, W_hh, b_ih, b_hh);

    for (int it = 0; it < NITERS; it++) {
        lstm_mma<<<dim3(16, 16), 128>>>(out, it);
        attn_pass<<<BGRAPHS, 256>>>(feat, out, it);
    }
    // After it=5 (odd), out holds [h6 | readout6] = q_star. No final copy needed.
}